// round 8
// baseline (speedup 1.0000x reference)
#include <cuda_runtime.h>
#include <cuda_bf16.h>

// QuantumLayer analytic collapse:
//   out[b,i] = prod_{c <= i, ((i-c) & (L-1)) == 0} cos(x[b,c])
// RZ layers are unit-modulus diagonal phases -> cancel in |.|^2; the CNOT
// chain is the GF(2) prefix-sum matrix M; Z_i after L layers pulls back to
// the parity set = row i of M^L, (M^L)_{ic} = C(i-c+L-1, L-1) mod 2, odd iff
// ((i-c) & (L-1)) == 0 (Kummer). Product measure -> the parity expectation
// factorizes into prod cos(x_c). q_weights is mathematically irrelevant.
//
// L=2 specialization: even/odd chains are component-pure over float2 pairs:
//   out[b, 2h]   = prod_{g<=h} cos(x[b, 2g])
//   out[b, 2h+1] = prod_{g<=h} cos(x[b, 2g+1])
//
// Perf notes: kernel time is pinned at ~4us (launch + one DRAM round trip);
// keep grid >= 148 (sm_103a low-grid throttle inflates wall time); minimize
// total warps and use 64-bit memory ops to shorten launch/drain.

constexpr int N  = 10;       // wires (q_weights.shape[1]); even
constexpr int NP = N / 2;    // float2 pairs per row

// One thread per output PAIR. <=NP independent predicated LDG.64, MUFU cos,
// two short FMUL chains, one STG.64. No sync, no guard on exact fit.
template<bool EXACT>
__global__ __launch_bounds__(128)
void quantum_pair2_kernel(const float* __restrict__ x,
                          float* __restrict__ out, int npairs) {
    int t = blockIdx.x * blockDim.x + threadIdx.x;
    if (!EXACT && t >= npairs) return;
    int b  = t / NP;               // constexpr divisor -> mul/shift
    int pm = t - b * NP;           // pair index within row, 0..NP-1
    const float2* rx = (const float2*)(x + b * N);

    float p0 = 1.0f, p1 = 1.0f;
    #pragma unroll
    for (int h = 0; h < NP; h++) {
        if (h <= pm) {
            float2 v = __ldg(rx + h);
            p0 *= __cosf(v.x);
            p1 *= __cosf(v.y);
        }
    }
    ((float2*)out)[t] = make_float2(p0, p1);
}

// Generic fallback: any L, Kummer mask rule, one thread per element.
__global__ __launch_bounds__(256)
void quantum_generic_kernel(const float* __restrict__ x,
                            float* __restrict__ out,
                            int total, int Lm1) {
    int t = blockIdx.x * blockDim.x + threadIdx.x;
    if (t >= total) return;
    int b = t / N;
    int i = t - b * N;
    const float* row = x + b * N;
    float p = 1.0f;
    #pragma unroll
    for (int c = i; c >= 0; --c)
        if (((i - c) & Lm1) == 0)
            p *= __cosf(__ldg(row + c));
    out[t] = p;
}

extern "C" void kernel_launch(void* const* d_in, const int* in_sizes, int n_in,
                              void* d_out, int out_size) {
    const float* x = (const float*)d_in[0];
    // d_in[1] = q_weights: unused (phases cancel in probabilities)
    const int L = in_sizes[1] / N;   // layers
    float* out = (float*)d_out;

    if (L == 2) {
        const int npairs  = out_size / 2;            // B * NP
        const int threads = 128;                     // grid stays >= 148
        const int blocks  = (npairs + threads - 1) / threads;
        if (npairs % threads == 0)
            quantum_pair2_kernel<true><<<blocks, threads>>>(x, out, npairs);
        else
            quantum_pair2_kernel<false><<<blocks, threads>>>(x, out, npairs);
    } else {
        const int total   = out_size;
        const int threads = 256;
        const int blocks  = (total + threads - 1) / threads;
        quantum_generic_kernel<<<blocks, threads>>>(x, out, total, L - 1);
    }
}

// round 9
// speedup vs baseline: 1.0601x; 1.0601x over previous
#include <cuda_runtime.h>
#include <cuda_bf16.h>

// QuantumLayer analytic collapse:
//   out[b,i] = prod_{c <= i, ((i-c) & (L-1)) == 0} cos(x[b,c])
// Derivation: RZ layers are unit-modulus diagonal phases -> cancel in |.|^2;
// the CNOT chain is the GF(2) prefix-sum matrix M; Z_i after L layers pulls
// back to the parity set = row i of M^L, (M^L)_{ic} = C(i-c+L-1, L-1) mod 2,
// odd iff ((i-c) & (L-1)) == 0 (Kummer). The initial state is a product
// measure, so the parity expectation factorizes into prod cos(x_c).
// q_weights is mathematically irrelevant to the output.
//
// Perf conclusions (R1-R8): every implementation pins the kernel at ~4.0us =
// launch overhead + one DRAM round trip (DRAM/L2/pipes all <1%). Wall-clock
// replay overhead is minimized by the LARGEST launch tried (160 blocks x 256
// threads, one thread per element); smaller launches inflate wall time
// (sm_103a low-grid clock throttle). This config measured best: 4.93us.

constexpr int N = 10;   // wires (q_weights.shape[1])

// Specialized: power-of-2 L -> membership is stride-L. One thread per output
// element; <=ceil(N/L) independent predicated loads + MUFU cos, no sync.
template<int L>
__global__ __launch_bounds__(256)
void quantum_elem_kernel(const float* __restrict__ x,
                         float* __restrict__ out, int total) {
    int t = blockIdx.x * blockDim.x + threadIdx.x;
    if (t >= total) return;
    int b = t / N;            // constexpr divisor -> mul/shift, no IDIV
    int i = t - b * N;
    const float* row = x + b * N;

    float p = __cosf(__ldg(row + i));
    #pragma unroll
    for (int k = 1; k * L < N; k++) {
        int c = i - k * L;
        if (c >= 0) p *= __cosf(__ldg(row + c));
    }
    out[t] = p;
}

// Generic fallback: any L, Kummer mask rule.
__global__ __launch_bounds__(256)
void quantum_generic_kernel(const float* __restrict__ x,
                            float* __restrict__ out,
                            int total, int Lm1) {
    int t = blockIdx.x * blockDim.x + threadIdx.x;
    if (t >= total) return;
    int b = t / N;
    int i = t - b * N;
    const float* row = x + b * N;
    float p = 1.0f;
    #pragma unroll
    for (int c = i; c >= 0; --c)
        if (((i - c) & Lm1) == 0)
            p *= __cosf(__ldg(row + c));
    out[t] = p;
}

extern "C" void kernel_launch(void* const* d_in, const int* in_sizes, int n_in,
                              void* d_out, int out_size) {
    const float* x = (const float*)d_in[0];
    // d_in[1] = q_weights: unused (phases cancel in probabilities)
    const int L = in_sizes[1] / N;   // layers
    const int total = out_size;      // B * N
    float* out = (float*)d_out;

    const int threads = 256;
    const int blocks = (total + threads - 1) / threads;

    switch (L) {
        case 1: quantum_elem_kernel<1><<<blocks, threads>>>(x, out, total); break;
        case 2: quantum_elem_kernel<2><<<blocks, threads>>>(x, out, total); break;
        case 4: quantum_elem_kernel<4><<<blocks, threads>>>(x, out, total); break;
        case 8: quantum_elem_kernel<8><<<blocks, threads>>>(x, out, total); break;
        default:
            quantum_generic_kernel<<<blocks, threads>>>(x, out, total, L - 1);
    }
}